// round 2
// baseline (speedup 1.0000x reference)
#include <cuda_runtime.h>
#include <cuda_bf16.h>
#include <math.h>

// ---------------------------------------------------------------------------
// OptimizedMambaBlock: B=8, DIM=256, H=W=32 -> L=1024, tokens N=8192
// D_INNER=512, D_STATE=16, D_CONV=4, DT_RANK=16
// Pipeline:
//   ln1(+transpose) -> in_proj GEMM -> conv+silu -> x_proj GEMM -> dt proj
//   -> selective scan (fused gate) -> out_proj GEMM (+res)
//   -> ln2 -> mlp1 GEMM (+gelu) -> mlp2 GEMM (+res, transposed store)
// ---------------------------------------------------------------------------

#define NTOK   8192
#define LSEQ   1024
#define BSZ    8
#define DIMC   256
#define DINNER 512
#define DSTATE 16
#define DTRANK 16

// scratch (device globals: allocation-free per harness rules)
__device__ float g_xf [NTOK * DIMC];     // residual stream (token-major)
__device__ float g_xn [NTOK * DIMC];     // ln1 output
__device__ float g_xz [NTOK * 1024];     // in_proj output (xi | z)
__device__ float g_xc [NTOK * DINNER];   // conv+silu output
__device__ float g_dbl[NTOK * 48];       // x_proj output (dt_r | B | C)
__device__ float g_dt [NTOK * DINNER];   // softplus(dt)
__device__ float g_y  [NTOK * DINNER];   // scan output * silu(z)
__device__ float g_xf2[NTOK * DIMC];     // after out_proj residual
__device__ float g_hln[NTOK * DIMC];     // ln2 output
__device__ float g_h1 [NTOK * 1024];     // mlp hidden

// ---------------------------------------------------------------------------
// LN1 + transpose: x (B,256,L) -> xf, xn (token-major N x 256)
// one block per token, 256 threads (one per channel)
// ---------------------------------------------------------------------------
__global__ void ln1_kernel(const float* __restrict__ x,
                           const float* __restrict__ g,
                           const float* __restrict__ bta) {
    __shared__ float red[16];
    int token = blockIdx.x;
    int c = threadIdx.x;
    int b = token >> 10, t = token & 1023;
    float v = x[((size_t)b * DIMC + c) * LSEQ + t];
    float s = v, q = v * v;
    #pragma unroll
    for (int o = 16; o; o >>= 1) {
        s += __shfl_xor_sync(~0u, s, o);
        q += __shfl_xor_sync(~0u, q, o);
    }
    int w = c >> 5, l = c & 31;
    if (l == 0) { red[w] = s; red[8 + w] = q; }
    __syncthreads();
    s = 0.f; q = 0.f;
    #pragma unroll
    for (int i = 0; i < 8; i++) { s += red[i]; q += red[8 + i]; }
    float mean = s * (1.f / 256.f);
    float var  = q * (1.f / 256.f) - mean * mean;
    float rs = rsqrtf(var + 1e-5f);
    size_t o = (size_t)token * DIMC + c;
    g_xf[o] = v;
    g_xn[o] = (v - mean) * rs * g[c] + bta[c];
}

// ---------------------------------------------------------------------------
// LN2: xf2 (token-major) -> hln. warp per token, 8 tokens per block.
// ---------------------------------------------------------------------------
__global__ void ln2_kernel(const float* __restrict__ g,
                           const float* __restrict__ bta) {
    int token = (blockIdx.x * blockDim.x + threadIdx.x) >> 5;
    int lane = threadIdx.x & 31;
    const float* row = g_xf2 + (size_t)token * DIMC;
    float4 a = *(const float4*)(row + lane * 4);
    float4 c4 = *(const float4*)(row + 128 + lane * 4);
    float s = a.x + a.y + a.z + a.w + c4.x + c4.y + c4.z + c4.w;
    float q = a.x*a.x + a.y*a.y + a.z*a.z + a.w*a.w
            + c4.x*c4.x + c4.y*c4.y + c4.z*c4.z + c4.w*c4.w;
    #pragma unroll
    for (int o = 16; o; o >>= 1) {
        s += __shfl_xor_sync(~0u, s, o);
        q += __shfl_xor_sync(~0u, q, o);
    }
    float mean = s * (1.f / 256.f);
    float var  = q * (1.f / 256.f) - mean * mean;
    float rs = rsqrtf(var + 1e-5f);
    float* out = g_hln + (size_t)token * DIMC;
    const float* vin[2] = { (const float*)&a, (const float*)&c4 };
    #pragma unroll
    for (int h = 0; h < 2; h++) {
        #pragma unroll
        for (int i = 0; i < 4; i++) {
            int c = h * 128 + lane * 4 + i;
            out[c] = (vin[h][i] - mean) * rs * g[c] + bta[c];
        }
    }
}

// ---------------------------------------------------------------------------
// causal depthwise conv (k=4) + silu over the xi half of xz -> xc
// ---------------------------------------------------------------------------
__global__ void conv_silu_kernel(const float* __restrict__ cw,
                                 const float* __restrict__ cb) {
    int idx = blockIdx.x * blockDim.x + threadIdx.x;   // (token, d)
    int token = idx >> 9;
    int d = idx & 511;
    int t = token & 1023;
    int tokbase = token - t;  // first token of this batch row
    float acc = cb[d];
    #pragma unroll
    for (int j = 0; j < 4; j++) {
        int tt = t - 3 + j;
        if (tt >= 0)
            acc += g_xz[(size_t)(tokbase + tt) * 1024 + d] * cw[d * 4 + j];
    }
    float sv = acc / (1.f + __expf(-acc));
    g_xc[(size_t)token * DINNER + d] = sv;
}

// ---------------------------------------------------------------------------
// dt projection: dt = softplus(dbl[:, :16] @ dtw^T + dtb) -> (N, 512)
// block handles 8 tokens x 512 d; weight staged transposed in smem
// ---------------------------------------------------------------------------
__global__ void dt_kernel(const float* __restrict__ dtw,
                          const float* __restrict__ dtb) {
    __shared__ float swT[16][512];
    int tid = threadIdx.x;
    for (int idx = tid; idx < 512 * 16; idx += 256) {
        int d = idx >> 4, r = idx & 15;
        swT[r][d] = dtw[idx];
    }
    __syncthreads();
    int t0 = blockIdx.x * 8;
    for (int o = tid; o < 8 * 512; o += 256) {
        int tl = o >> 9, d = o & 511;
        int token = t0 + tl;
        const float* row = g_dbl + (size_t)token * 48;
        float acc = dtb[d];
        #pragma unroll
        for (int r = 0; r < 16; r++)
            acc += row[r] * swT[r][d];
        float sp = (acc > 20.f) ? acc : log1pf(__expf(acc));
        g_dt[(size_t)token * DINNER + d] = sp;
    }
}

// ---------------------------------------------------------------------------
// selective scan + gating.
// Lane layout: 4 lanes per (b,d) group, each lane owns 4 states.
// 8 groups per warp, 32 groups per 128-thread block, 128 blocks total.
// ---------------------------------------------------------------------------
__global__ void scan_kernel(const float* __restrict__ A_log,
                            const float* __restrict__ Dp) {
    int tid = threadIdx.x;
    int b  = blockIdx.x >> 4;
    int d  = ((blockIdx.x & 15) << 5) + (tid >> 2);
    int sq = tid & 3;

    float Al[4], h[4];
    #pragma unroll
    for (int j = 0; j < 4; j++) {
        Al[j] = -__expf(A_log[d * 16 + sq * 4 + j]) * 1.44269504f; // A*log2(e)
        h[j] = 0.f;
    }
    float dpv = Dp[d];

    const float* dtp  = g_dt  + (size_t)b * LSEQ * DINNER + d;
    const float* up   = g_xc  + (size_t)b * LSEQ * DINNER + d;
    const float* dblp = g_dbl + (size_t)b * LSEQ * 48;
    const float* zp   = g_xz  + (size_t)b * LSEQ * 1024 + 512 + d;
    float*       yp   = g_y   + (size_t)b * LSEQ * DINNER + d;

    for (int t = 0; t < LSEQ; t++) {
        float dt = dtp[(size_t)t * DINNER];
        float u  = up [(size_t)t * DINNER];
        float4 Bv = *(const float4*)(dblp + (size_t)t * 48 + 16 + sq * 4);
        float4 Cv = *(const float4*)(dblp + (size_t)t * 48 + 32 + sq * 4);
        float dtu = dt * u;
        float y = 0.f;
        h[0] = exp2f(dt * Al[0]) * h[0] + dtu * Bv.x; y += h[0] * Cv.x;
        h[1] = exp2f(dt * Al[1]) * h[1] + dtu * Bv.y; y += h[1] * Cv.y;
        h[2] = exp2f(dt * Al[2]) * h[2] + dtu * Bv.z; y += h[2] * Cv.z;
        h[3] = exp2f(dt * Al[3]) * h[3] + dtu * Bv.w; y += h[3] * Cv.w;
        y += __shfl_xor_sync(~0u, y, 1);
        y += __shfl_xor_sync(~0u, y, 2);
        if (sq == 0) {
            float z = zp[(size_t)t * 1024];
            float gate = z / (1.f + __expf(-z));
            yp[(size_t)t * DINNER] = (y + u * dpv) * gate;
        }
    }
}

// ---------------------------------------------------------------------------
// Tiled SGEMM (NT): C[M,N] = A[M,K] @ B[N,K]^T, with epilogues.
// BM=128, BN=64, BK=16, 256 threads, 8x4 microtile.
// EPI: 0 plain | 1 +res | 2 gelu(acc+bias) | 3 res+acc+bias, transposed store
// ---------------------------------------------------------------------------
template <int EPI>
__global__ void sgemm_nt(const float* __restrict__ A,
                         const float* __restrict__ B,
                         float* __restrict__ C,
                         int M, int N, int K,
                         const float* __restrict__ bias,
                         const float* __restrict__ res) {
    const int BM = 128, BN = 64, BK = 16;
    __shared__ float As[BK][BM];
    __shared__ float Bs[BK][BN];

    int tid = threadIdx.x;
    int m0 = blockIdx.y * BM, n0 = blockIdx.x * BN;
    int tx = tid & 15, ty = tid >> 4;

    int lrow = tid >> 2;            // 0..63
    int lkc  = (tid & 3) << 2;      // 0,4,8,12

    float acc[8][4];
    #pragma unroll
    for (int i = 0; i < 8; i++)
        #pragma unroll
        for (int j = 0; j < 4; j++) acc[i][j] = 0.f;

    for (int kt = 0; kt < K; kt += BK) {
        // A tile: 128x16, transposed into As[k][m]
        const float* Ap = A + (size_t)(m0 + lrow) * K + kt + lkc;
        float4 a0 = *(const float4*)Ap;
        float4 a1 = *(const float4*)(Ap + (size_t)64 * K);
        As[lkc + 0][lrow] = a0.x; As[lkc + 1][lrow] = a0.y;
        As[lkc + 2][lrow] = a0.z; As[lkc + 3][lrow] = a0.w;
        As[lkc + 0][lrow + 64] = a1.x; As[lkc + 1][lrow + 64] = a1.y;
        As[lkc + 2][lrow + 64] = a1.z; As[lkc + 3][lrow + 64] = a1.w;
        // B tile: 64x16 (guard N)
        float4 bv = make_float4(0.f, 0.f, 0.f, 0.f);
        if (n0 + lrow < N)
            bv = *(const float4*)(B + (size_t)(n0 + lrow) * K + kt + lkc);
        Bs[lkc + 0][lrow] = bv.x; Bs[lkc + 1][lrow] = bv.y;
        Bs[lkc + 2][lrow] = bv.z; Bs[lkc + 3][lrow] = bv.w;
        __syncthreads();
        #pragma unroll
        for (int k = 0; k < BK; k++) {
            float4 af0 = *(const float4*)&As[k][ty * 8];
            float4 af1 = *(const float4*)&As[k][ty * 8 + 4];
            float4 bf  = *(const float4*)&Bs[k][tx * 4];
            float av[8] = { af0.x, af0.y, af0.z, af0.w, af1.x, af1.y, af1.z, af1.w };
            float bw[4] = { bf.x, bf.y, bf.z, bf.w };
            #pragma unroll
            for (int i = 0; i < 8; i++)
                #pragma unroll
                for (int j = 0; j < 4; j++)
                    acc[i][j] += av[i] * bw[j];
        }
        __syncthreads();
    }

    #pragma unroll
    for (int i = 0; i < 8; i++) {
        int m = m0 + ty * 8 + i;
        #pragma unroll
        for (int j = 0; j < 4; j++) {
            int n = n0 + tx * 4 + j;
            if (n >= N) continue;
            float v = acc[i][j];
            if (EPI == 0) {
                C[(size_t)m * N + n] = v;
            } else if (EPI == 1) {
                C[(size_t)m * N + n] = res[(size_t)m * N + n] + v;
            } else if (EPI == 2) {
                float u = v + bias[n];
                C[(size_t)m * N + n] = 0.5f * u * (1.f + erff(u * 0.70710678118f));
            } else { // EPI == 3: final residual + transposed store (B,256,L)
                float u = res[(size_t)m * N + n] + v + bias[n];
                int b = m >> 10, t = m & 1023;
                C[((size_t)b * DIMC + n) * LSEQ + t] = u;
            }
        }
    }
}

// ---------------------------------------------------------------------------
extern "C" void kernel_launch(void* const* d_in, const int* in_sizes, int n_in,
                              void* d_out, int out_size) {
    const float* x        = (const float*)d_in[0];
    const float* ln_g     = (const float*)d_in[1];
    const float* ln_b     = (const float*)d_in[2];
    const float* in_proj  = (const float*)d_in[3];
    const float* conv_w   = (const float*)d_in[4];
    const float* conv_b   = (const float*)d_in[5];
    const float* x_proj   = (const float*)d_in[6];
    const float* dt_w     = (const float*)d_in[7];
    const float* dt_b     = (const float*)d_in[8];
    const float* A_log    = (const float*)d_in[9];
    const float* Dp       = (const float*)d_in[10];
    const float* out_proj = (const float*)d_in[11];
    const float* mlp_ln_g = (const float*)d_in[12];
    const float* mlp_ln_b = (const float*)d_in[13];
    const float* mlp_w1   = (const float*)d_in[14];
    const float* mlp_b1   = (const float*)d_in[15];
    const float* mlp_w2   = (const float*)d_in[16];
    const float* mlp_b2   = (const float*)d_in[17];
    float* out = (float*)d_out;

    float *p_xn, *p_xz, *p_xc, *p_dbl, *p_y, *p_xf, *p_xf2, *p_hln, *p_h1;
    cudaGetSymbolAddress((void**)&p_xn,  g_xn);
    cudaGetSymbolAddress((void**)&p_xz,  g_xz);
    cudaGetSymbolAddress((void**)&p_xc,  g_xc);
    cudaGetSymbolAddress((void**)&p_dbl, g_dbl);
    cudaGetSymbolAddress((void**)&p_y,   g_y);
    cudaGetSymbolAddress((void**)&p_xf,  g_xf);
    cudaGetSymbolAddress((void**)&p_xf2, g_xf2);
    cudaGetSymbolAddress((void**)&p_hln, g_hln);
    cudaGetSymbolAddress((void**)&p_h1,  g_h1);

    // 1. ln1 + transpose
    ln1_kernel<<<NTOK, 256>>>(x, ln_g, ln_b);
    // 2. in_proj: xz = xn @ W^T   (8192 x 1024, K=256)
    sgemm_nt<0><<<dim3(1024 / 64, NTOK / 128), 256>>>(p_xn, in_proj, p_xz,
                                                      NTOK, 1024, 256, nullptr, nullptr);
    // 3. conv + silu
    conv_silu_kernel<<<(NTOK * DINNER) / 256, 256>>>(conv_w, conv_b);
    // 4. x_proj: dbl = xc @ W^T   (8192 x 48, K=512)
    sgemm_nt<0><<<dim3(1, NTOK / 128), 256>>>(p_xc, x_proj, p_dbl,
                                              NTOK, 48, 512, nullptr, nullptr);
    // 5. dt projection + softplus
    dt_kernel<<<NTOK / 8, 256>>>(dt_w, dt_b);
    // 6. selective scan + gating
    scan_kernel<<<128, 128>>>(A_log, Dp);
    // 7. out_proj + residual: xf2 = xf + y @ W^T   (8192 x 256, K=512)
    sgemm_nt<1><<<dim3(256 / 64, NTOK / 128), 256>>>(p_y, out_proj, p_xf2,
                                                     NTOK, 256, 512, nullptr, p_xf);
    // 8. ln2
    ln2_kernel<<<NTOK / 8, 256>>>(mlp_ln_g, mlp_ln_b);
    // 9. mlp1 + gelu: h1 = gelu(hln @ W1^T + b1)   (8192 x 1024, K=256)
    sgemm_nt<2><<<dim3(1024 / 64, NTOK / 128), 256>>>(p_hln, mlp_w1, p_h1,
                                                      NTOK, 1024, 256, mlp_b1, nullptr);
    // 10. mlp2 + residual + transposed store  (8192 x 256, K=1024)
    sgemm_nt<3><<<dim3(256 / 64, NTOK / 128), 256>>>(p_h1, mlp_w2, out,
                                                     NTOK, 256, 1024, mlp_b2, p_xf2);
}